// round 2
// baseline (speedup 1.0000x reference)
#include <cuda_runtime.h>
#include <math.h>

// Problem constants
#define BATCH 32768
#define HID   512
#define T_HIST 50

#define BT 64    // batch tile
#define JT 32    // hidden-unit tile
#define KC 16    // K chunk

// Ping-pong hidden state buffers (device globals: allocation-free scratch)
__device__ float g_h0a[BATCH * HID];
__device__ float g_h0b[BATCH * HID];
__device__ float g_h1a[BATCH * HID];
__device__ float g_h1b[BATCH * HID];

__device__ __forceinline__ float sigmoidf_(float x) {
    return 1.0f / (1.0f + __expf(-x));
}
__device__ __forceinline__ float tanhf_(float x) {
    // accurate enough (__expf ~2 ulp), clamp avoids inf/inf
    x = fminf(15.0f, fmaxf(-15.0f, x));
    float e = __expf(2.0f * x);
    return (e - 1.0f) / (e + 1.0f);
}

__global__ void zero_kernel(float* a, float* b, int n) {
    int i = blockIdx.x * blockDim.x + threadIdx.x;
    int stride = gridDim.x * blockDim.x;
    for (; i < n; i += stride) { a[i] = 0.0f; b[i] = 0.0f; }
}

// Fused GRU cell: h_out = GRUCell(x, h_in)
// x: [B, DX] rows with row stride x_stride (floats)
// W_ih: [3H, DX], W_hh: [3H, H] (row-major, PyTorch layout), gates ordered (r,z,n)
template <int DX>
__global__ void __launch_bounds__(256, 2)
gru_cell_kernel(const float* __restrict__ x, int x_stride,
                const float* __restrict__ h_in,
                const float* __restrict__ W_ih,
                const float* __restrict__ W_hh,
                const float* __restrict__ b_ih,
                const float* __restrict__ b_hh,
                float* __restrict__ h_out)
{
    __shared__ float sh[BT][KC + 1];            // h chunk (padded)
    __shared__ float sx[BT][KC + 1];            // x chunk (only used DX==512)
    __shared__ float swh[3][JT][KC + 1];        // W_hh chunk per gate (padded)
    __shared__ float swi[3][JT][KC + 1];        // W_ih chunk per gate

    const int tid = threadIdx.x;
    const int tx = tid & 15;       // j dim: 2 cols each
    const int ty = tid >> 4;       // b dim: 4 rows each
    const int b0 = blockIdx.x * BT;
    const int j0 = blockIdx.y * JT;

    float accI[3][4][2];
    float accH[3][4][2];
#pragma unroll
    for (int g = 0; g < 3; g++)
#pragma unroll
        for (int r = 0; r < 4; r++) {
            accI[g][r][0] = 0.f; accI[g][r][1] = 0.f;
            accH[g][r][0] = 0.f; accH[g][r][1] = 0.f;
        }

    if (DX == 3) {
        // tiny input GEMM done directly from gmem (weights are L1/L2-resident)
#pragma unroll
        for (int r = 0; r < 4; r++) {
            int b = b0 + ty * 4 + r;
            float x0 = __ldg(&x[(size_t)b * x_stride + 0]);
            float x1 = __ldg(&x[(size_t)b * x_stride + 1]);
            float x2 = __ldg(&x[(size_t)b * x_stride + 2]);
#pragma unroll
            for (int g = 0; g < 3; g++) {
#pragma unroll
                for (int cc = 0; cc < 2; cc++) {
                    int j = j0 + tx * 2 + cc;
                    const float* wr = &W_ih[(size_t)(g * HID + j) * 3];
                    accI[g][r][cc] = x0 * __ldg(&wr[0]) + x1 * __ldg(&wr[1]) + x2 * __ldg(&wr[2]);
                }
            }
        }
    }

    // main K loop over hidden dim (and x dim when DX==512)
    for (int k0 = 0; k0 < HID; k0 += KC) {
        // load h chunk: 64x16 floats, one float4 per thread
        {
            int lr = tid >> 2;
            int lc = (tid & 3) * 4;
            float4 hv = *(const float4*)&h_in[(size_t)(b0 + lr) * HID + k0 + lc];
            sh[lr][lc + 0] = hv.x; sh[lr][lc + 1] = hv.y;
            sh[lr][lc + 2] = hv.z; sh[lr][lc + 3] = hv.w;
            if (DX == 512) {
                float4 xv = *(const float4*)&x[(size_t)(b0 + lr) * x_stride + k0 + lc];
                sx[lr][lc + 0] = xv.x; sx[lr][lc + 1] = xv.y;
                sx[lr][lc + 2] = xv.z; sx[lr][lc + 3] = xv.w;
            }
        }
        // load weight chunks: 3 gates x 32 rows x 16 = 384 float4 per matrix
        for (int idx = tid; idx < 3 * JT * 4; idx += 256) {
            int g  = idx / (JT * 4);
            int rm = idx % (JT * 4);
            int jj = rm >> 2;
            int c4 = (rm & 3) * 4;
            float4 wv = *(const float4*)&W_hh[(size_t)(g * HID + j0 + jj) * HID + k0 + c4];
            swh[g][jj][c4 + 0] = wv.x; swh[g][jj][c4 + 1] = wv.y;
            swh[g][jj][c4 + 2] = wv.z; swh[g][jj][c4 + 3] = wv.w;
            if (DX == 512) {
                float4 wi = *(const float4*)&W_ih[(size_t)(g * HID + j0 + jj) * 512 + k0 + c4];
                swi[g][jj][c4 + 0] = wi.x; swi[g][jj][c4 + 1] = wi.y;
                swi[g][jj][c4 + 2] = wi.z; swi[g][jj][c4 + 3] = wi.w;
            }
        }
        __syncthreads();

#pragma unroll
        for (int k = 0; k < KC; k++) {
            float ah[4], ax[4];
#pragma unroll
            for (int r = 0; r < 4; r++) {
                ah[r] = sh[ty * 4 + r][k];
                if (DX == 512) ax[r] = sx[ty * 4 + r][k];
            }
#pragma unroll
            for (int g = 0; g < 3; g++) {
#pragma unroll
                for (int cc = 0; cc < 2; cc++) {
                    float wh = swh[g][tx * 2 + cc][k];
#pragma unroll
                    for (int r = 0; r < 4; r++)
                        accH[g][r][cc] += ah[r] * wh;
                    if (DX == 512) {
                        float wi = swi[g][tx * 2 + cc][k];
#pragma unroll
                        for (int r = 0; r < 4; r++)
                            accI[g][r][cc] += ax[r] * wi;
                    }
                }
            }
        }
        __syncthreads();
    }

    // epilogue: gate math
#pragma unroll
    for (int r = 0; r < 4; r++) {
#pragma unroll
        for (int cc = 0; cc < 2; cc++) {
            int b = b0 + ty * 4 + r;
            int j = j0 + tx * 2 + cc;
            float gir = accI[0][r][cc] + b_ih[j];
            float giz = accI[1][r][cc] + b_ih[HID + j];
            float gin = accI[2][r][cc] + b_ih[2 * HID + j];
            float ghr = accH[0][r][cc] + b_hh[j];
            float ghz = accH[1][r][cc] + b_hh[HID + j];
            float ghn = accH[2][r][cc] + b_hh[2 * HID + j];
            float rg = sigmoidf_(gir + ghr);
            float zg = sigmoidf_(giz + ghz);
            float nv = tanhf_(gin + rg * ghn);
            float hp = h_in[(size_t)b * HID + j];
            h_out[(size_t)b * HID + j] = (1.0f - zg) * nv + zg * hp;
        }
    }
}

// Output head: out[b] = h[b] @ fc_W^T + fc_b, one warp per batch row
__global__ void fc_kernel(const float* __restrict__ h,
                          const float* __restrict__ fc_W,
                          const float* __restrict__ fc_b,
                          float* __restrict__ out, int out_stride)
{
    int warp = (blockIdx.x * blockDim.x + threadIdx.x) >> 5;
    int lane = threadIdx.x & 31;
    if (warp >= BATCH) return;
    float a0 = 0.f, a1 = 0.f, a2 = 0.f;
    for (int k = lane; k < HID; k += 32) {
        float hv = h[(size_t)warp * HID + k];
        a0 += hv * fc_W[k];
        a1 += hv * fc_W[HID + k];
        a2 += hv * fc_W[2 * HID + k];
    }
#pragma unroll
    for (int off = 16; off > 0; off >>= 1) {
        a0 += __shfl_down_sync(0xffffffffu, a0, off);
        a1 += __shfl_down_sync(0xffffffffu, a1, off);
        a2 += __shfl_down_sync(0xffffffffu, a2, off);
    }
    if (lane == 0) {
        float* o = &out[(size_t)warp * out_stride];
        o[0] = a0 + fc_b[0];
        o[1] = a1 + fc_b[1];
        o[2] = a2 + fc_b[2];
    }
}

extern "C" void kernel_launch(void* const* d_in, const int* in_sizes, int n_in,
                              void* d_out, int out_size)
{
    const float* x_input   = (const float*)d_in[0];
    // d_in[1] = future_len (derived from out_size instead)
    const float* enc_W_ih0 = (const float*)d_in[2];
    const float* enc_W_hh0 = (const float*)d_in[3];
    const float* enc_b_ih0 = (const float*)d_in[4];
    const float* enc_b_hh0 = (const float*)d_in[5];
    const float* enc_W_ih1 = (const float*)d_in[6];
    const float* enc_W_hh1 = (const float*)d_in[7];
    const float* enc_b_ih1 = (const float*)d_in[8];
    const float* enc_b_hh1 = (const float*)d_in[9];
    const float* dec_W_ih0 = (const float*)d_in[10];
    const float* dec_W_hh0 = (const float*)d_in[11];
    const float* dec_b_ih0 = (const float*)d_in[12];
    const float* dec_b_hh0 = (const float*)d_in[13];
    const float* dec_W_ih1 = (const float*)d_in[14];
    const float* dec_W_hh1 = (const float*)d_in[15];
    const float* dec_b_ih1 = (const float*)d_in[16];
    const float* dec_b_hh1 = (const float*)d_in[17];
    const float* fc_W      = (const float*)d_in[18];
    const float* fc_b      = (const float*)d_in[19];
    float* out = (float*)d_out;

    const int F = out_size / (BATCH * 3);   // future_len (30)

    float *h0[2], *h1[2];
    cudaGetSymbolAddress((void**)&h0[0], g_h0a);
    cudaGetSymbolAddress((void**)&h0[1], g_h0b);
    cudaGetSymbolAddress((void**)&h1[0], g_h1a);
    cudaGetSymbolAddress((void**)&h1[1], g_h1b);

    // zero initial hidden states (must happen every call: graph replays)
    zero_kernel<<<2048, 256>>>(h0[0], h1[0], BATCH * HID);

    dim3 grid(BATCH / BT, HID / JT);   // (512, 16)
    int p0 = 0, p1 = 0;

    // ---- encoder ----
    for (int t = 0; t < T_HIST; t++) {
        gru_cell_kernel<3><<<grid, 256>>>(x_input + t * 3, T_HIST * 3,
                                          h0[p0],
                                          enc_W_ih0, enc_W_hh0, enc_b_ih0, enc_b_hh0,
                                          h0[1 - p0]);
        p0 ^= 1;
        gru_cell_kernel<512><<<grid, 256>>>(h0[p0], HID,
                                            h1[p1],
                                            enc_W_ih1, enc_W_hh1, enc_b_ih1, enc_b_hh1,
                                            h1[1 - p1]);
        p1 ^= 1;
    }

    // ---- decoder ----
    for (int t = 0; t < F; t++) {
        const float* xin = (t == 0) ? (x_input + (T_HIST - 1) * 3) : (out + (t - 1) * 3);
        int xs = (t == 0) ? (T_HIST * 3) : (F * 3);
        gru_cell_kernel<3><<<grid, 256>>>(xin, xs,
                                          h0[p0],
                                          dec_W_ih0, dec_W_hh0, dec_b_ih0, dec_b_hh0,
                                          h0[1 - p0]);
        p0 ^= 1;
        gru_cell_kernel<512><<<grid, 256>>>(h0[p0], HID,
                                            h1[p1],
                                            dec_W_ih1, dec_W_hh1, dec_b_ih1, dec_b_hh1,
                                            h1[1 - p1]);
        p1 ^= 1;
        fc_kernel<<<(BATCH * 32) / 256, 256>>>(h1[p1], fc_W, fc_b, out + t * 3, F * 3);
    }
}

// round 5
// speedup vs baseline: 2.0467x; 2.0467x over previous
#include <cuda_runtime.h>
#include <cuda_bf16.h>
#include <math.h>
#include <stdint.h>

#define BATCH 32768
#define HID   512
#define T_HIST 50
#define BM 128      // batch tile
#define BJ 32       // hidden cols per gate per CTA
#define KC 16       // K chunk (one mma k16)
#define PS 24       // padded smem row stride (bf16) -> conflict-free ldmatrix

typedef __nv_bfloat16 bf16;

// ---------------- device-global scratch (allocation-free) ----------------
// hidden-state planes (hi/lo bf16 split), ping-pong
__device__ bf16 g_h0hi[2][(size_t)BATCH * HID];
__device__ bf16 g_h0lo[2][(size_t)BATCH * HID];
__device__ bf16 g_h1hi[2][(size_t)BATCH * HID];
__device__ bf16 g_h1lo[2][(size_t)BATCH * HID];
// split weights: [0]=enc_hh0 [1]=enc_ih1 [2]=enc_hh1 [3]=dec_hh0 [4]=dec_ih1 [5]=dec_hh1
#define WELEMS ((size_t)3 * HID * HID)
__device__ bf16 g_whi[6][WELEMS];
__device__ bf16 g_wlo[6][WELEMS];

// ---------------- helpers ----------------
__device__ __forceinline__ float sigmoidf_(float x) { return 1.0f / (1.0f + __expf(-x)); }
__device__ __forceinline__ float tanhf_(float x) {
    x = fminf(15.0f, fmaxf(-15.0f, x));
    float e = __expf(2.0f * x);
    return (e - 1.0f) / (e + 1.0f);
}
__device__ __forceinline__ uint32_t smem_u32(const void* p) {
    return (uint32_t)__cvta_generic_to_shared(p);
}
__device__ __forceinline__ void cp16(uint32_t dst, const void* src) {
    asm volatile("cp.async.cg.shared.global [%0], [%1], 16;" :: "r"(dst), "l"(src));
}
__device__ __forceinline__ void cp_commit() { asm volatile("cp.async.commit_group;"); }
__device__ __forceinline__ void ldsm4(uint32_t& r0, uint32_t& r1, uint32_t& r2, uint32_t& r3, uint32_t addr) {
    asm volatile("ldmatrix.sync.aligned.m8n8.x4.shared.b16 {%0,%1,%2,%3}, [%4];"
                 : "=r"(r0), "=r"(r1), "=r"(r2), "=r"(r3) : "r"(addr));
}
__device__ __forceinline__ void mma16816(float* c, const uint32_t* a, const uint32_t* b) {
    asm volatile("mma.sync.aligned.m16n8k16.row.col.f32.bf16.bf16.f32 "
                 "{%0,%1,%2,%3}, {%4,%5,%6,%7}, {%8,%9}, {%0,%1,%2,%3};"
                 : "+f"(c[0]), "+f"(c[1]), "+f"(c[2]), "+f"(c[3])
                 : "r"(a[0]), "r"(a[1]), "r"(a[2]), "r"(a[3]), "r"(b[0]), "r"(b[1]));
}

// ---------------- setup kernels ----------------
__global__ void prep_split_kernel(const float* w0, const float* w1, const float* w2,
                                  const float* w3, const float* w4, const float* w5) {
    const float* srcs[6] = {w0, w1, w2, w3, w4, w5};
    size_t total = 6 * WELEMS;
    for (size_t i = (size_t)blockIdx.x * blockDim.x + threadIdx.x; i < total;
         i += (size_t)gridDim.x * blockDim.x) {
        int m = (int)(i / WELEMS);
        size_t e = i % WELEMS;
        float v = srcs[m][e];
        bf16 hi = __float2bfloat16(v);
        bf16 lo = __float2bfloat16(v - __bfloat162float(hi));
        g_whi[m][e] = hi;
        g_wlo[m][e] = lo;
    }
}

__global__ void zero_planes_kernel() {
    size_t n = (size_t)BATCH * HID;
    bf16 z = __float2bfloat16(0.0f);
    for (size_t i = (size_t)blockIdx.x * blockDim.x + threadIdx.x; i < n;
         i += (size_t)gridDim.x * blockDim.x) {
        g_h0hi[0][i] = z; g_h0lo[0][i] = z;
        g_h1hi[0][i] = z; g_h1lo[0][i] = z;
    }
}

// ---------------- fused GRU cell on tensor cores ----------------
// WITHX=true : layer-1 cell, x = bf16 plane pair (full 512-wide GEMM on W_ih)
// WITHX=false: layer-0 cell, x = fp32 [B,3], W_ih0 applied in fp32 epilogue
template <bool WITHX>
__global__ void __launch_bounds__(256, 1)
gru_mma_kernel(const bf16* __restrict__ xhi, const bf16* __restrict__ xlo,
               const float* __restrict__ x3, int x3_stride,
               const bf16* __restrict__ hhi, const bf16* __restrict__ hlo,
               const bf16* __restrict__ wihi, const bf16* __restrict__ wilo,
               const float* __restrict__ wih3,
               const bf16* __restrict__ whhi, const bf16* __restrict__ whlo,
               const float* __restrict__ b_ih, const float* __restrict__ b_hh,
               bf16* __restrict__ ohi, bf16* __restrict__ olo)
{
    extern __shared__ bf16 smem[];
    constexpr int APL = BM * PS;                 // A plane: 128 rows x PS
    constexpr int WPL = 96 * PS;                 // W plane: 96 rows (3 gates x 32) x PS
    constexpr int NA = WITHX ? 4 : 2;            // A planes: h_hi,h_lo[,x_hi,x_lo]
    constexpr int NW = WITHX ? 4 : 2;            // W planes: whh_hi,whh_lo[,wih_hi,wih_lo]
    constexpr int STAGE = NA * APL + NW * WPL;
    constexpr int NSLAB = WITHX ? 6 : 3;         // slabs 0..2 = hh gates, 3..5 = ih gates
    constexpr int NCH = HID / KC;                // 32 K-chunks

    const int tid  = threadIdx.x;
    const int lane = tid & 31;
    const int warp = tid >> 5;
    const int b0 = blockIdx.x * BM;
    const int j0 = blockIdx.y * BJ;
    const int gid = lane >> 2, tig = lane & 3;

    const bf16* gA[4] = { hhi, hlo, xhi, xlo };
    const bf16* gW[4] = { whhi, whlo, wihi, wilo };

    float acc[NSLAB][4][4];
#pragma unroll
    for (int s = 0; s < NSLAB; s++)
#pragma unroll
        for (int nb = 0; nb < 4; nb++)
#pragma unroll
            for (int k = 0; k < 4; k++) acc[s][nb][k] = 0.0f;

    auto load_stage = [&](int st_idx, int c) {
        bf16* st = smem + st_idx * STAGE;
        const int k0 = c * KC;
        // A planes: NA * 128 rows * 2 segs (16B each)
        for (int i = tid; i < NA * 256; i += 256) {
            int pl = i >> 8, rem = i & 255;
            int row = rem >> 1, seg = rem & 1;
            const bf16* src = gA[pl] + (size_t)(b0 + row) * HID + k0 + seg * 8;
            cp16(smem_u32(st + pl * APL + row * PS + seg * 8), src);
        }
        // W planes: NW * 96 rows * 2 segs
        for (int i = tid; i < NW * 192; i += 256) {
            int pl = i / 192, rem = i % 192;
            int row = rem >> 1, seg = rem & 1;
            int g = row >> 5, r = row & 31;
            const bf16* src = gW[pl] + (size_t)(g * HID + j0 + r) * HID + k0 + seg * 8;
            cp16(smem_u32(st + NA * APL + pl * WPL + row * PS + seg * 8), src);
        }
        cp_commit();
    };

    auto compute = [&](int st_idx) {
        bf16* st = smem + st_idx * STAGE;
        // A fragments for all planes (warp handles rows warp*16..warp*16+15)
        uint32_t Af[NA][4];
        const int a_row = lane & 15;
        const int a_col = (lane >> 4) * 8;
#pragma unroll
        for (int pl = 0; pl < NA; pl++) {
            uint32_t addr = smem_u32(st + pl * APL + (warp * 16 + a_row) * PS + a_col);
            ldsm4(Af[pl][0], Af[pl][1], Af[pl][2], Af[pl][3], addr);
        }
        const int q = lane >> 3, mr = lane & 7;
#pragma unroll
        for (int slab = 0; slab < NSLAB; slab++) {
            const int wmat = slab / 3;   // 0 = hh, 1 = ih
            const int g = slab % 3;
            uint32_t Bf[2][4][2];        // [hi/lo plane][nb][b0,b1]
#pragma unroll
            for (int wpl = 0; wpl < 2; wpl++) {
                bf16* base = st + NA * APL + (wmat * 2 + wpl) * WPL + (g * 32) * PS;
#pragma unroll
                for (int half = 0; half < 2; half++) {
                    uint32_t addr = smem_u32(base + (half * 16 + (q >> 1) * 8 + mr) * PS + (q & 1) * 8);
                    ldsm4(Bf[wpl][half * 2][0], Bf[wpl][half * 2][1],
                          Bf[wpl][half * 2 + 1][0], Bf[wpl][half * 2 + 1][1], addr);
                }
            }
            const uint32_t* Ahi = Af[wmat * 2];
            const uint32_t* Alo = Af[wmat * 2 + 1];
#pragma unroll
            for (int nb = 0; nb < 4; nb++) {
                mma16816(acc[slab][nb], Ahi, Bf[0][nb]);   // hi*hi
                mma16816(acc[slab][nb], Ahi, Bf[1][nb]);   // hi*lo
                mma16816(acc[slab][nb], Alo, Bf[0][nb]);   // lo*hi
            }
        }
    };

    load_stage(0, 0);
    for (int c = 0; c < NCH; c++) {
        int s = c & 1;
        if (c + 1 < NCH) {
            load_stage(s ^ 1, c + 1);
            asm volatile("cp.async.wait_group 1;");
        } else {
            asm volatile("cp.async.wait_group 0;");
        }
        __syncthreads();
        compute(s);
        __syncthreads();
    }

    // ---------------- epilogue: gate math ----------------
#pragma unroll
    for (int half = 0; half < 2; half++) {
        const int b = b0 + warp * 16 + gid + half * 8;
        float x0f = 0.f, x1f = 0.f, x2f = 0.f;
        if (!WITHX) {
            x0f = x3[(size_t)b * x3_stride + 0];
            x1f = x3[(size_t)b * x3_stride + 1];
            x2f = x3[(size_t)b * x3_stride + 2];
        }
#pragma unroll
        for (int nb = 0; nb < 4; nb++) {
#pragma unroll
            for (int cc = 0; cc < 2; cc++) {
                const int j = j0 + nb * 8 + 2 * tig + cc;
                const int fi = half * 2 + cc;
                float hr = acc[0][nb][fi] + b_hh[j];
                float hz = acc[1][nb][fi] + b_hh[HID + j];
                float hn = acc[2][nb][fi] + b_hh[2 * HID + j];
                float ir, iz, in_;
                if (WITHX) {
                    ir  = acc[3][nb][fi] + b_ih[j];
                    iz  = acc[4][nb][fi] + b_ih[HID + j];
                    in_ = acc[5][nb][fi] + b_ih[2 * HID + j];
                } else {
                    const float* w0 = &wih3[(size_t)(0 * HID + j) * 3];
                    const float* w1 = &wih3[(size_t)(1 * HID + j) * 3];
                    const float* w2 = &wih3[(size_t)(2 * HID + j) * 3];
                    ir  = x0f * w0[0] + x1f * w0[1] + x2f * w0[2] + b_ih[j];
                    iz  = x0f * w1[0] + x1f * w1[1] + x2f * w1[2] + b_ih[HID + j];
                    in_ = x0f * w2[0] + x1f * w2[1] + x2f * w2[2] + b_ih[2 * HID + j];
                }
                float r = sigmoidf_(ir + hr);
                float z = sigmoidf_(iz + hz);
                float n = tanhf_(in_ + r * hn);
                size_t idx = (size_t)b * HID + j;
                float hp = __bfloat162float(hhi[idx]) + __bfloat162float(hlo[idx]);
                float hnew = (1.0f - z) * n + z * hp;
                bf16 hi = __float2bfloat16(hnew);
                bf16 lo = __float2bfloat16(hnew - __bfloat162float(hi));
                ohi[idx] = hi;
                olo[idx] = lo;
            }
        }
    }
}

// ---------------- output head ----------------
__global__ void fc_kernel(const bf16* __restrict__ hhi, const bf16* __restrict__ hlo,
                          const float* __restrict__ fc_W, const float* __restrict__ fc_b,
                          float* __restrict__ out, int out_stride)
{
    int warp = (blockIdx.x * blockDim.x + threadIdx.x) >> 5;
    int lane = threadIdx.x & 31;
    if (warp >= BATCH) return;
    float a0 = 0.f, a1 = 0.f, a2 = 0.f;
    for (int k = lane; k < HID; k += 32) {
        size_t idx = (size_t)warp * HID + k;
        float hv = __bfloat162float(hhi[idx]) + __bfloat162float(hlo[idx]);
        a0 += hv * fc_W[k];
        a1 += hv * fc_W[HID + k];
        a2 += hv * fc_W[2 * HID + k];
    }
#pragma unroll
    for (int off = 16; off > 0; off >>= 1) {
        a0 += __shfl_down_sync(0xffffffffu, a0, off);
        a1 += __shfl_down_sync(0xffffffffu, a1, off);
        a2 += __shfl_down_sync(0xffffffffu, a2, off);
    }
    if (lane == 0) {
        float* o = &out[(size_t)warp * out_stride];
        o[0] = a0 + fc_b[0];
        o[1] = a1 + fc_b[1];
        o[2] = a2 + fc_b[2];
    }
}

// ---------------- launcher ----------------
extern "C" void kernel_launch(void* const* d_in, const int* in_sizes, int n_in,
                              void* d_out, int out_size)
{
    const float* x_input   = (const float*)d_in[0];
    const float* enc_W_ih0 = (const float*)d_in[2];
    const float* enc_W_hh0 = (const float*)d_in[3];
    const float* enc_b_ih0 = (const float*)d_in[4];
    const float* enc_b_hh0 = (const float*)d_in[5];
    const float* enc_W_ih1 = (const float*)d_in[6];
    const float* enc_W_hh1 = (const float*)d_in[7];
    const float* enc_b_ih1 = (const float*)d_in[8];
    const float* enc_b_hh1 = (const float*)d_in[9];
    const float* dec_W_ih0 = (const float*)d_in[10];
    const float* dec_W_hh0 = (const float*)d_in[11];
    const float* dec_b_ih0 = (const float*)d_in[12];
    const float* dec_b_hh0 = (const float*)d_in[13];
    const float* dec_W_ih1 = (const float*)d_in[14];
    const float* dec_W_hh1 = (const float*)d_in[15];
    const float* dec_b_ih1 = (const float*)d_in[16];
    const float* dec_b_hh1 = (const float*)d_in[17];
    const float* fc_W      = (const float*)d_in[18];
    const float* fc_b      = (const float*)d_in[19];
    float* out = (float*)d_out;

    const int F = out_size / (BATCH * 3);

    // dynamic smem sizes
    const int stage1 = (4 * BM * PS + 4 * 96 * PS) * (int)sizeof(bf16);
    const int stage0 = (2 * BM * PS + 2 * 96 * PS) * (int)sizeof(bf16);
    cudaFuncSetAttribute(gru_mma_kernel<true>,  cudaFuncAttributeMaxDynamicSharedMemorySize, 2 * stage1);
    cudaFuncSetAttribute(gru_mma_kernel<false>, cudaFuncAttributeMaxDynamicSharedMemorySize, 2 * stage0);

    // symbol addresses
    bf16 *h0hi_b, *h0lo_b, *h1hi_b, *h1lo_b, *whi_b, *wlo_b;
    cudaGetSymbolAddress((void**)&h0hi_b, g_h0hi);
    cudaGetSymbolAddress((void**)&h0lo_b, g_h0lo);
    cudaGetSymbolAddress((void**)&h1hi_b, g_h1hi);
    cudaGetSymbolAddress((void**)&h1lo_b, g_h1lo);
    cudaGetSymbolAddress((void**)&whi_b, g_whi);
    cudaGetSymbolAddress((void**)&wlo_b, g_wlo);
    const size_t HN = (size_t)BATCH * HID;
    bf16* h0hi[2] = { h0hi_b, h0hi_b + HN };
    bf16* h0lo[2] = { h0lo_b, h0lo_b + HN };
    bf16* h1hi[2] = { h1hi_b, h1hi_b + HN };
    bf16* h1lo[2] = { h1lo_b, h1lo_b + HN };
    auto WHI = [&](int m) { return whi_b + (size_t)m * WELEMS; };
    auto WLO = [&](int m) { return wlo_b + (size_t)m * WELEMS; };

    // per-call setup (graph replays must be deterministic)
    prep_split_kernel<<<2048, 256>>>(enc_W_hh0, enc_W_ih1, enc_W_hh1,
                                     dec_W_hh0, dec_W_ih1, dec_W_hh1);
    zero_planes_kernel<<<2048, 256>>>();

    dim3 grid(BATCH / BM, HID / BJ);   // (256, 16)
    int p0 = 0, p1 = 0;

    // ---- encoder ----
    for (int t = 0; t < T_HIST; t++) {
        gru_mma_kernel<false><<<grid, 256, 2 * stage0>>>(
            nullptr, nullptr, x_input + t * 3, T_HIST * 3,
            h0hi[p0], h0lo[p0],
            nullptr, nullptr, enc_W_ih0,
            WHI(0), WLO(0),
            enc_b_ih0, enc_b_hh0,
            h0hi[p0 ^ 1], h0lo[p0 ^ 1]);
        p0 ^= 1;
        gru_mma_kernel<true><<<grid, 256, 2 * stage1>>>(
            h0hi[p0], h0lo[p0], nullptr, 0,
            h1hi[p1], h1lo[p1],
            WHI(1), WLO(1), nullptr,
            WHI(2), WLO(2),
            enc_b_ih1, enc_b_hh1,
            h1hi[p1 ^ 1], h1lo[p1 ^ 1]);
        p1 ^= 1;
    }

    // ---- decoder ----
    for (int t = 0; t < F; t++) {
        const float* xin = (t == 0) ? (x_input + (T_HIST - 1) * 3) : (out + (t - 1) * 3);
        int xs = (t == 0) ? (T_HIST * 3) : (F * 3);
        gru_mma_kernel<false><<<grid, 256, 2 * stage0>>>(
            nullptr, nullptr, xin, xs,
            h0hi[p0], h0lo[p0],
            nullptr, nullptr, dec_W_ih0,
            WHI(3), WLO(3),
            dec_b_ih0, dec_b_hh0,
            h0hi[p0 ^ 1], h0lo[p0 ^ 1]);
        p0 ^= 1;
        gru_mma_kernel<true><<<grid, 256, 2 * stage1>>>(
            h0hi[p0], h0lo[p0], nullptr, 0,
            h1hi[p1], h1lo[p1],
            WHI(4), WLO(4), nullptr,
            WHI(5), WLO(5),
            dec_b_ih1, dec_b_hh1,
            h1hi[p1 ^ 1], h1lo[p1 ^ 1]);
        p1 ^= 1;
        fc_kernel<<<(BATCH * 32) / 256, 256>>>(h1hi[p1], h1lo[p1], fc_W, fc_b,
                                               out + t * 3, F * 3);
    }
}

// round 6
// speedup vs baseline: 2.2362x; 1.0926x over previous
#include <cuda_runtime.h>
#include <cuda_bf16.h>
#include <math.h>
#include <stdint.h>

#define BATCH 32768
#define HID   512
#define T_HIST 50
#define BM 128      // batch tile
#define BJ 32       // hidden cols per gate per CTA
#define KC 16       // K chunk (one mma k16)
#define PS 24       // padded smem row stride (bf16)
#define NST 3       // pipeline stages
#define NCH (HID / KC)

typedef __nv_bfloat16 bf16;

// ---------------- device-global scratch (allocation-free) ----------------
__device__ bf16 g_h0hi[2][(size_t)BATCH * HID];
__device__ bf16 g_h0lo[2][(size_t)BATCH * HID];
__device__ bf16 g_h1hi[2][(size_t)BATCH * HID];
__device__ bf16 g_h1lo[2][(size_t)BATCH * HID];
#define WELEMS ((size_t)3 * HID * HID)
__device__ bf16 g_whi[6][WELEMS];
__device__ bf16 g_wlo[6][WELEMS];

// ---------------- helpers ----------------
__device__ __forceinline__ float sigmoidf_(float x) { return 1.0f / (1.0f + __expf(-x)); }
__device__ __forceinline__ float tanhf_(float x) {
    x = fminf(15.0f, fmaxf(-15.0f, x));
    float e = __expf(2.0f * x);
    return (e - 1.0f) / (e + 1.0f);
}
__device__ __forceinline__ uint32_t smem_u32(const void* p) {
    return (uint32_t)__cvta_generic_to_shared(p);
}
__device__ __forceinline__ void cp16(uint32_t dst, const void* src) {
    asm volatile("cp.async.cg.shared.global [%0], [%1], 16;" :: "r"(dst), "l"(src));
}
__device__ __forceinline__ void cp_commit() { asm volatile("cp.async.commit_group;"); }
__device__ __forceinline__ void ldsm4(uint32_t& r0, uint32_t& r1, uint32_t& r2, uint32_t& r3, uint32_t addr) {
    asm volatile("ldmatrix.sync.aligned.m8n8.x4.shared.b16 {%0,%1,%2,%3}, [%4];"
                 : "=r"(r0), "=r"(r1), "=r"(r2), "=r"(r3) : "r"(addr));
}
__device__ __forceinline__ void mma16816(float* c, const uint32_t* a, const uint32_t* b) {
    asm volatile("mma.sync.aligned.m16n8k16.row.col.f32.bf16.bf16.f32 "
                 "{%0,%1,%2,%3}, {%4,%5,%6,%7}, {%8,%9}, {%0,%1,%2,%3};"
                 : "+f"(c[0]), "+f"(c[1]), "+f"(c[2]), "+f"(c[3])
                 : "r"(a[0]), "r"(a[1]), "r"(a[2]), "r"(a[3]), "r"(b[0]), "r"(b[1]));
}

// ---------------- setup kernels ----------------
__global__ void prep_split_kernel(const float* w0, const float* w1, const float* w2,
                                  const float* w3, const float* w4, const float* w5) {
    const float* srcs[6] = {w0, w1, w2, w3, w4, w5};
    size_t total = 6 * WELEMS;
    for (size_t i = (size_t)blockIdx.x * blockDim.x + threadIdx.x; i < total;
         i += (size_t)gridDim.x * blockDim.x) {
        int m = (int)(i / WELEMS);
        size_t e = i % WELEMS;
        float v = srcs[m][e];
        bf16 hi = __float2bfloat16(v);
        bf16 lo = __float2bfloat16(v - __bfloat162float(hi));
        g_whi[m][e] = hi;
        g_wlo[m][e] = lo;
    }
}

__global__ void zero_planes_kernel() {
    size_t n = (size_t)BATCH * HID;
    bf16 z = __float2bfloat16(0.0f);
    for (size_t i = (size_t)blockIdx.x * blockDim.x + threadIdx.x; i < n;
         i += (size_t)gridDim.x * blockDim.x) {
        g_h0hi[0][i] = z; g_h0lo[0][i] = z;
        g_h1hi[0][i] = z; g_h1lo[0][i] = z;
    }
}

// ---------------- fused GRU cell on tensor cores ----------------
// WITHX=true : 512 threads; warps 0-7 compute W_hh slabs (A = h planes),
//              warps 8-15 compute W_ih slabs (A = x planes); smem exchange.
// WITHX=false: 256 threads; W_hh slabs only; W_ih0 (D=3) applied in fp32 epilogue.
template <bool WITHX>
__global__ void __launch_bounds__(WITHX ? 512 : 256, WITHX ? 1 : 2)
gru_mma_kernel(const bf16* __restrict__ xhi, const bf16* __restrict__ xlo,
               const float* __restrict__ x3, int x3_stride,
               const bf16* __restrict__ hhi, const bf16* __restrict__ hlo,
               const bf16* __restrict__ wihi, const bf16* __restrict__ wilo,
               const float* __restrict__ wih3,
               const bf16* __restrict__ whhi, const bf16* __restrict__ whlo,
               const float* __restrict__ b_ih, const float* __restrict__ b_hh,
               bf16* __restrict__ ohi, bf16* __restrict__ olo)
{
    extern __shared__ bf16 smem[];
    constexpr int APL = BM * PS;
    constexpr int WPL = 96 * PS;
    constexpr int NA = WITHX ? 4 : 2;
    constexpr int NW = WITHX ? 4 : 2;
    constexpr int STAGE = NA * APL + NW * WPL;
    constexpr int THREADS = WITHX ? 512 : 256;
    constexpr int EXS = 33;   // exchange row stride (floats)

    const int tid  = threadIdx.x;
    const int lane = tid & 31;
    const int warp = tid >> 5;
    const int grp  = WITHX ? (warp >> 3) : 0;   // 0 = hh group, 1 = ih group
    const int wig  = warp & 7;                  // warp in group: rows wig*16..+15
    const int b0 = blockIdx.x * BM;
    const int j0 = blockIdx.y * BJ;
    const int gid = lane >> 2, tig = lane & 3;

    const bf16* gA[4] = { hhi, hlo, xhi, xlo };
    const bf16* gW[4] = { whhi, whlo, wihi, wilo };

    float acc[3][4][4];
#pragma unroll
    for (int s = 0; s < 3; s++)
#pragma unroll
        for (int nb = 0; nb < 4; nb++)
#pragma unroll
            for (int k = 0; k < 4; k++) acc[s][nb][k] = 0.0f;

    auto load_stage = [&](int slot, int c) {
        bf16* st = smem + slot * STAGE;
        const int k0 = c * KC;
        // A planes: NA * 128 rows * 2 segs of 16B
#pragma unroll
        for (int i = tid; i < NA * 256; i += THREADS) {
            int pl = i >> 8, rem = i & 255;
            int row = rem >> 1, seg = rem & 1;
            cp16(smem_u32(st + pl * APL + row * PS + seg * 8),
                 gA[pl] + (size_t)(b0 + row) * HID + k0 + seg * 8);
        }
        // W planes: NW * 96 rows * 2 segs
#pragma unroll
        for (int i = tid; i < NW * 192; i += THREADS) {
            int pl = i / 192, rem = i % 192;
            int row = rem >> 1, seg = rem & 1;
            int g = row >> 5, r = row & 31;
            cp16(smem_u32(st + NA * APL + pl * WPL + row * PS + seg * 8),
                 gW[pl] + (size_t)(g * HID + j0 + r) * HID + k0 + seg * 8);
        }
        cp_commit();
    };

    const int wmat = grp;   // which (A,W) plane pair this group consumes

    auto compute = [&](int slot) {
        bf16* st = smem + slot * STAGE;
        uint32_t Af[2][4];
        const int a_row = lane & 15;
        const int a_col = (lane >> 4) * 8;
#pragma unroll
        for (int pl = 0; pl < 2; pl++) {
            uint32_t addr = smem_u32(st + (wmat * 2 + pl) * APL + (wig * 16 + a_row) * PS + a_col);
            ldsm4(Af[pl][0], Af[pl][1], Af[pl][2], Af[pl][3], addr);
        }
        const int q = lane >> 3, mr = lane & 7;
#pragma unroll
        for (int g = 0; g < 3; g++) {
            uint32_t Bf[2][4][2];
#pragma unroll
            for (int wpl = 0; wpl < 2; wpl++) {
                bf16* base = st + NA * APL + (wmat * 2 + wpl) * WPL + (g * 32) * PS;
#pragma unroll
                for (int half = 0; half < 2; half++) {
                    uint32_t addr = smem_u32(base + (half * 16 + (q >> 1) * 8 + mr) * PS + (q & 1) * 8);
                    ldsm4(Bf[wpl][half * 2][0], Bf[wpl][half * 2][1],
                          Bf[wpl][half * 2 + 1][0], Bf[wpl][half * 2 + 1][1], addr);
                }
            }
#pragma unroll
            for (int nb = 0; nb < 4; nb++) {
                mma16816(acc[g][nb], Af[0], Bf[0][nb]);   // hi*hi
                mma16816(acc[g][nb], Af[0], Bf[1][nb]);   // hi*lo
                mma16816(acc[g][nb], Af[1], Bf[0][nb]);   // lo*hi
            }
        }
    };

    // ---- 3-stage pipeline, one sync per chunk ----
    load_stage(0, 0);
    load_stage(1, 1);
    for (int c = 0; c < NCH; c++) {
        if (c + 1 < NCH) asm volatile("cp.async.wait_group 1;");
        else             asm volatile("cp.async.wait_group 0;");
        __syncthreads();
        if (c + 2 < NCH) load_stage((c + 2) % NST, c + 2);
        compute(c % NST);
    }

    // ---- epilogue ----
    float* exch = (float*)smem;   // overlay on dead pipeline stages
    __syncthreads();              // all compute done before overlay write

    if (WITHX && grp == 1) {
#pragma unroll
        for (int half = 0; half < 2; half++) {
            const int row = wig * 16 + gid + half * 8;
#pragma unroll
            for (int nb = 0; nb < 4; nb++)
#pragma unroll
                for (int cc = 0; cc < 2; cc++) {
                    const int col = nb * 8 + 2 * tig + cc;
                    const int fi = half * 2 + cc;
#pragma unroll
                    for (int g = 0; g < 3; g++)
                        exch[(g * BM + row) * EXS + col] = acc[g][nb][fi];
                }
        }
    }
    if (WITHX) __syncthreads();

    if (grp == 0) {
#pragma unroll
        for (int half = 0; half < 2; half++) {
            const int row = wig * 16 + gid + half * 8;
            const int b = b0 + row;
            float x0f = 0.f, x1f = 0.f, x2f = 0.f;
            if (!WITHX) {
                x0f = x3[(size_t)b * x3_stride + 0];
                x1f = x3[(size_t)b * x3_stride + 1];
                x2f = x3[(size_t)b * x3_stride + 2];
            }
#pragma unroll
            for (int nb = 0; nb < 4; nb++) {
#pragma unroll
                for (int cc = 0; cc < 2; cc++) {
                    const int col = nb * 8 + 2 * tig + cc;
                    const int j = j0 + col;
                    const int fi = half * 2 + cc;
                    float hr = acc[0][nb][fi] + b_hh[j];
                    float hz = acc[1][nb][fi] + b_hh[HID + j];
                    float hn = acc[2][nb][fi] + b_hh[2 * HID + j];
                    float ir, iz, in_;
                    if (WITHX) {
                        ir  = exch[(0 * BM + row) * EXS + col] + b_ih[j];
                        iz  = exch[(1 * BM + row) * EXS + col] + b_ih[HID + j];
                        in_ = exch[(2 * BM + row) * EXS + col] + b_ih[2 * HID + j];
                    } else {
                        const float* w0 = &wih3[(size_t)(0 * HID + j) * 3];
                        const float* w1 = &wih3[(size_t)(1 * HID + j) * 3];
                        const float* w2 = &wih3[(size_t)(2 * HID + j) * 3];
                        ir  = x0f * w0[0] + x1f * w0[1] + x2f * w0[2] + b_ih[j];
                        iz  = x0f * w1[0] + x1f * w1[1] + x2f * w1[2] + b_ih[HID + j];
                        in_ = x0f * w2[0] + x1f * w2[1] + x2f * w2[2] + b_ih[2 * HID + j];
                    }
                    float r = sigmoidf_(ir + hr);
                    float z = sigmoidf_(iz + hz);
                    float n = tanhf_(in_ + r * hn);
                    size_t idx = (size_t)b * HID + j;
                    float hp = __bfloat162float(hhi[idx]) + __bfloat162float(hlo[idx]);
                    float hnew = (1.0f - z) * n + z * hp;
                    bf16 hi = __float2bfloat16(hnew);
                    bf16 lo = __float2bfloat16(hnew - __bfloat162float(hi));
                    ohi[idx] = hi;
                    olo[idx] = lo;
                }
            }
        }
    }
}

// ---------------- output head ----------------
__global__ void fc_kernel(const bf16* __restrict__ hhi, const bf16* __restrict__ hlo,
                          const float* __restrict__ fc_W, const float* __restrict__ fc_b,
                          float* __restrict__ out, int out_stride)
{
    int warp = (blockIdx.x * blockDim.x + threadIdx.x) >> 5;
    int lane = threadIdx.x & 31;
    if (warp >= BATCH) return;
    float a0 = 0.f, a1 = 0.f, a2 = 0.f;
    for (int k = lane; k < HID; k += 32) {
        size_t idx = (size_t)warp * HID + k;
        float hv = __bfloat162float(hhi[idx]) + __bfloat162float(hlo[idx]);
        a0 += hv * fc_W[k];
        a1 += hv * fc_W[HID + k];
        a2 += hv * fc_W[2 * HID + k];
    }
#pragma unroll
    for (int off = 16; off > 0; off >>= 1) {
        a0 += __shfl_down_sync(0xffffffffu, a0, off);
        a1 += __shfl_down_sync(0xffffffffu, a1, off);
        a2 += __shfl_down_sync(0xffffffffu, a2, off);
    }
    if (lane == 0) {
        float* o = &out[(size_t)warp * out_stride];
        o[0] = a0 + fc_b[0];
        o[1] = a1 + fc_b[1];
        o[2] = a2 + fc_b[2];
    }
}

// ---------------- launcher ----------------
extern "C" void kernel_launch(void* const* d_in, const int* in_sizes, int n_in,
                              void* d_out, int out_size)
{
    const float* x_input   = (const float*)d_in[0];
    const float* enc_W_ih0 = (const float*)d_in[2];
    const float* enc_W_hh0 = (const float*)d_in[3];
    const float* enc_b_ih0 = (const float*)d_in[4];
    const float* enc_b_hh0 = (const float*)d_in[5];
    const float* enc_W_ih1 = (const float*)d_in[6];
    const float* enc_W_hh1 = (const float*)d_in[7];
    const float* enc_b_ih1 = (const float*)d_in[8];
    const float* enc_b_hh1 = (const float*)d_in[9];
    const float* dec_W_ih0 = (const float*)d_in[10];
    const float* dec_W_hh0 = (const float*)d_in[11];
    const float* dec_b_ih0 = (const float*)d_in[12];
    const float* dec_b_hh0 = (const float*)d_in[13];
    const float* dec_W_ih1 = (const float*)d_in[14];
    const float* dec_W_hh1 = (const float*)d_in[15];
    const float* dec_b_ih1 = (const float*)d_in[16];
    const float* dec_b_hh1 = (const float*)d_in[17];
    const float* fc_W      = (const float*)d_in[18];
    const float* fc_b      = (const float*)d_in[19];
    float* out = (float*)d_out;

    const int F = out_size / (BATCH * 3);

    const int stage1 = (4 * BM * PS + 4 * 96 * PS) * (int)sizeof(bf16);
    const int stage0 = (2 * BM * PS + 2 * 96 * PS) * (int)sizeof(bf16);
    cudaFuncSetAttribute(gru_mma_kernel<true>,  cudaFuncAttributeMaxDynamicSharedMemorySize, NST * stage1);
    cudaFuncSetAttribute(gru_mma_kernel<false>, cudaFuncAttributeMaxDynamicSharedMemorySize, NST * stage0);

    bf16 *h0hi_b, *h0lo_b, *h1hi_b, *h1lo_b, *whi_b, *wlo_b;
    cudaGetSymbolAddress((void**)&h0hi_b, g_h0hi);
    cudaGetSymbolAddress((void**)&h0lo_b, g_h0lo);
    cudaGetSymbolAddress((void**)&h1hi_b, g_h1hi);
    cudaGetSymbolAddress((void**)&h1lo_b, g_h1lo);
    cudaGetSymbolAddress((void**)&whi_b, g_whi);
    cudaGetSymbolAddress((void**)&wlo_b, g_wlo);
    const size_t HN = (size_t)BATCH * HID;
    bf16* h0hi[2] = { h0hi_b, h0hi_b + HN };
    bf16* h0lo[2] = { h0lo_b, h0lo_b + HN };
    bf16* h1hi[2] = { h1hi_b, h1hi_b + HN };
    bf16* h1lo[2] = { h1lo_b, h1lo_b + HN };
    auto WHI = [&](int m) { return whi_b + (size_t)m * WELEMS; };
    auto WLO = [&](int m) { return wlo_b + (size_t)m * WELEMS; };

    prep_split_kernel<<<2048, 256>>>(enc_W_hh0, enc_W_ih1, enc_W_hh1,
                                     dec_W_hh0, dec_W_ih1, dec_W_hh1);
    zero_planes_kernel<<<2048, 256>>>();

    dim3 grid(BATCH / BM, HID / BJ);   // (256, 16)
    int p0 = 0, p1 = 0;

    // ---- encoder ----
    for (int t = 0; t < T_HIST; t++) {
        gru_mma_kernel<false><<<grid, 256, NST * stage0>>>(
            nullptr, nullptr, x_input + t * 3, T_HIST * 3,
            h0hi[p0], h0lo[p0],
            nullptr, nullptr, enc_W_ih0,
            WHI(0), WLO(0),
            enc_b_ih0, enc_b_hh0,
            h0hi[p0 ^ 1], h0lo[p0 ^ 1]);
        p0 ^= 1;
        gru_mma_kernel<true><<<grid, 512, NST * stage1>>>(
            h0hi[p0], h0lo[p0], nullptr, 0,
            h1hi[p1], h1lo[p1],
            WHI(1), WLO(1), nullptr,
            WHI(2), WLO(2),
            enc_b_ih1, enc_b_hh1,
            h1hi[p1 ^ 1], h1lo[p1 ^ 1]);
        p1 ^= 1;
    }

    // ---- decoder ----
    for (int t = 0; t < F; t++) {
        const float* xin = (t == 0) ? (x_input + (T_HIST - 1) * 3) : (out + (t - 1) * 3);
        int xs = (t == 0) ? (T_HIST * 3) : (F * 3);
        gru_mma_kernel<false><<<grid, 256, NST * stage0>>>(
            nullptr, nullptr, xin, xs,
            h0hi[p0], h0lo[p0],
            nullptr, nullptr, dec_W_ih0,
            WHI(3), WLO(3),
            dec_b_ih0, dec_b_hh0,
            h0hi[p0 ^ 1], h0lo[p0 ^ 1]);
        p0 ^= 1;
        gru_mma_kernel<true><<<grid, 512, NST * stage1>>>(
            h0hi[p0], h0lo[p0], nullptr, 0,
            h1hi[p1], h1lo[p1],
            WHI(4), WLO(4), nullptr,
            WHI(5), WLO(5),
            dec_b_ih1, dec_b_hh1,
            h1hi[p1 ^ 1], h1lo[p1 ^ 1]);
        p1 ^= 1;
        fc_kernel<<<(BATCH * 32) / 256, 256>>>(h1hi[p1], h1lo[p1], fc_W, fc_b,
                                               out + t * 3, F * 3);
    }
}

// round 8
// speedup vs baseline: 2.7911x; 1.2481x over previous
#include <cuda_runtime.h>
#include <cuda_fp16.h>
#include <math.h>
#include <stdint.h>

#define BATCH 32768
#define HID   512
#define T_HIST 50
#define BJ 32            // hidden cols per gate per CTA
#define KC 16            // K chunk (one mma k16)
#define PS 24            // padded smem row stride (halfs) -> conflict-free ldsm
#define NST 3            // pipeline stages
#define NCH (HID / KC)   // 32

typedef __half h16;

// ---------------- device-global scratch (allocation-free) ----------------
__device__ h16 g_h0[2][(size_t)BATCH * HID];
__device__ h16 g_h1[2][(size_t)BATCH * HID];
#define WELEMS ((size_t)3 * HID * HID)
// [0]=enc_hh0 [1]=enc_ih1 [2]=enc_hh1 [3]=dec_hh0 [4]=dec_ih1 [5]=dec_hh1
__device__ h16 g_w[6][WELEMS];

// ---------------- helpers ----------------
__device__ __forceinline__ float sigmoidf_(float x) { return 1.0f / (1.0f + __expf(-x)); }
__device__ __forceinline__ float tanhf_(float x) {
    x = fminf(15.0f, fmaxf(-15.0f, x));
    float e = __expf(2.0f * x);
    return (e - 1.0f) / (e + 1.0f);
}
__device__ __forceinline__ uint32_t smem_u32(const void* p) {
    return (uint32_t)__cvta_generic_to_shared(p);
}
__device__ __forceinline__ void cp16(uint32_t dst, const void* src) {
    asm volatile("cp.async.cg.shared.global [%0], [%1], 16;" :: "r"(dst), "l"(src));
}
__device__ __forceinline__ void cp_commit() { asm volatile("cp.async.commit_group;"); }
__device__ __forceinline__ void ldsm4(uint32_t& r0, uint32_t& r1, uint32_t& r2, uint32_t& r3, uint32_t addr) {
    asm volatile("ldmatrix.sync.aligned.m8n8.x4.shared.b16 {%0,%1,%2,%3}, [%4];"
                 : "=r"(r0), "=r"(r1), "=r"(r2), "=r"(r3) : "r"(addr));
}
__device__ __forceinline__ void mma16816(float* c, const uint32_t* a, const uint32_t* b) {
    asm volatile("mma.sync.aligned.m16n8k16.row.col.f32.f16.f16.f32 "
                 "{%0,%1,%2,%3}, {%4,%5,%6,%7}, {%8,%9}, {%0,%1,%2,%3};"
                 : "+f"(c[0]), "+f"(c[1]), "+f"(c[2]), "+f"(c[3])
                 : "r"(a[0]), "r"(a[1]), "r"(a[2]), "r"(a[3]), "r"(b[0]), "r"(b[1]));
}

// ---------------- setup kernels ----------------
__global__ void prep_kernel(const float* w0, const float* w1, const float* w2,
                            const float* w3, const float* w4, const float* w5) {
    const float* srcs[6] = {w0, w1, w2, w3, w4, w5};
    size_t total = 6 * WELEMS;
    for (size_t i = (size_t)blockIdx.x * blockDim.x + threadIdx.x; i < total;
         i += (size_t)gridDim.x * blockDim.x) {
        int m = (int)(i / WELEMS);
        size_t e = i % WELEMS;
        g_w[m][e] = __float2half(srcs[m][e]);
    }
}

__global__ void zero_kernel() {
    size_t n = (size_t)BATCH * HID;
    h16 z = __float2half(0.0f);
    for (size_t i = (size_t)blockIdx.x * blockDim.x + threadIdx.x; i < n;
         i += (size_t)gridDim.x * blockDim.x) {
        g_h0[0][i] = z;
        g_h1[0][i] = z;
    }
}

// ---------------- fused GRU cell on fp16 mma.sync ----------------
// WITHX=true : 8 warps, 2 groups of 4; group0: W_hh x h, group1: W_ih x x.
//              BM = 128 (both groups cover the same rows); smem exchange of ih gates.
// WITHX=false: 8 warps, single group, Mw=32 -> BM = 256; W_ih0 (D=3) in fp32 epilogue.
template <bool WITHX>
__global__ void __launch_bounds__(256, 1)
gru_mma_kernel(const h16* __restrict__ x16,
               const float* __restrict__ x3, int x3_stride,
               const h16* __restrict__ h_in,
               const h16* __restrict__ wih, const float* __restrict__ wih3,
               const h16* __restrict__ whh,
               const float* __restrict__ b_ih, const float* __restrict__ b_hh,
               h16* __restrict__ h_out)
{
    extern __shared__ h16 smem[];
    constexpr int BM   = WITHX ? 128 : 256;
    constexpr int AROWS = WITHX ? 128 : 256;     // rows per A plane
    constexpr int NA   = WITHX ? 2 : 1;
    constexpr int NW   = WITHX ? 2 : 1;
    constexpr int APL  = AROWS * PS;             // halfs per A plane
    constexpr int AOFF = NA * APL;               // == 6144 both cases
    constexpr int WPL  = 96 * PS;
    constexpr int STAGE = AOFF + NW * WPL;       // halfs
    constexpr int EXS = 33;                      // exchange row stride (floats)

    const int tid  = threadIdx.x;
    const int lane = tid & 31;
    const int warp = tid >> 5;
    const int grp  = WITHX ? (warp >> 2) : 0;
    const int wig  = WITHX ? (warp & 3) : warp;   // warp-in-group: rows wig*32..+31
    const int j0 = blockIdx.x * BJ;
    const int b0 = blockIdx.y * BM;
    const int gid = lane >> 2, tig = lane & 3;

    const h16* gA[2] = { h_in, x16 };
    const h16* gW[2] = { whh, wih };

    float acc[3][2][4][4];   // [gate][m-frag][nb][c]
#pragma unroll
    for (int g = 0; g < 3; g++)
#pragma unroll
        for (int m = 0; m < 2; m++)
#pragma unroll
            for (int nb = 0; nb < 4; nb++)
#pragma unroll
                for (int k = 0; k < 4; k++) acc[g][m][nb][k] = 0.0f;

    auto load_stage = [&](int slot, int c) {
        h16* st = smem + slot * STAGE;
        const int k0 = c * KC;
        // A planes: NA * AROWS rows * 2 segs of 16B  (= 512 cp16 both cases)
#pragma unroll
        for (int i = tid; i < NA * AROWS * 2; i += 256) {
            int pl  = WITHX ? (i >> 8) : 0;
            int rem = WITHX ? (i & 255) : i;
            int row = rem >> 1, seg = rem & 1;
            cp16(smem_u32(st + pl * APL + row * PS + seg * 8),
                 gA[pl] + (size_t)(b0 + row) * HID + k0 + seg * 8);
        }
        // W planes: NW * 96 rows * 2 segs
#pragma unroll
        for (int i = tid; i < NW * 192; i += 256) {
            int pl = i / 192, rem = i % 192;
            int row = rem >> 1, seg = rem & 1;
            int g = row >> 5, jj = row & 31;
            cp16(smem_u32(st + AOFF + pl * WPL + row * PS + seg * 8),
                 gW[pl] + (size_t)(g * HID + j0 + jj) * HID + k0 + seg * 8);
        }
        cp_commit();
    };

    auto compute = [&](int slot) {
        h16* st = smem + slot * STAGE;
        // A fragments: 2 x m16k16 (rows wig*32 .. +31) from this group's plane
        uint32_t Af[2][4];
        const int a_row = lane & 15;
        const int a_col = (lane >> 4) * 8;
#pragma unroll
        for (int m = 0; m < 2; m++) {
            uint32_t addr = smem_u32(st + grp * APL + (wig * 32 + m * 16 + a_row) * PS + a_col);
            ldsm4(Af[m][0], Af[m][1], Af[m][2], Af[m][3], addr);
        }
        const int q = lane >> 3, mr = lane & 7;
#pragma unroll
        for (int g = 0; g < 3; g++) {
            uint32_t Bf[4][2];
            h16* base = st + AOFF + grp * WPL + (g * 32) * PS;
#pragma unroll
            for (int half = 0; half < 2; half++) {
                uint32_t addr = smem_u32(base + (half * 16 + (q >> 1) * 8 + mr) * PS + (q & 1) * 8);
                ldsm4(Bf[half * 2][0], Bf[half * 2][1],
                      Bf[half * 2 + 1][0], Bf[half * 2 + 1][1], addr);
            }
#pragma unroll
            for (int m = 0; m < 2; m++)
#pragma unroll
                for (int nb = 0; nb < 4; nb++)
                    mma16816(acc[g][m][nb], Af[m], Bf[nb]);
        }
    };

    // ---- 3-stage pipeline, one sync per chunk ----
    load_stage(0, 0);
    load_stage(1, 1);
    for (int c = 0; c < NCH; c++) {
        if (c + 1 < NCH) asm volatile("cp.async.wait_group 1;");
        else             asm volatile("cp.async.wait_group 0;");
        __syncthreads();
        if (c + 2 < NCH) load_stage((c + 2) % NST, c + 2);
        compute(c % NST);
    }

    // ---- epilogue ----
    float* exch = (float*)smem;       // overlay on dead pipeline stages
    __syncthreads();                  // everyone done reading smem

    if (WITHX && grp == 1) {
        // publish ih gate pre-activations
#pragma unroll
        for (int m = 0; m < 2; m++)
#pragma unroll
            for (int h8 = 0; h8 < 2; h8++) {
                const int row = wig * 32 + m * 16 + gid + h8 * 8;
#pragma unroll
                for (int nb = 0; nb < 4; nb++)
#pragma unroll
                    for (int cc = 0; cc < 2; cc++) {
                        const int col = nb * 8 + tig * 2 + cc;
#pragma unroll
                        for (int g = 0; g < 3; g++)
                            exch[(g * 128 + row) * EXS + col] = acc[g][m][nb][h8 * 2 + cc];
                    }
            }
    }
    if (WITHX) __syncthreads();

    if (grp == 0) {
#pragma unroll
        for (int m = 0; m < 2; m++)
#pragma unroll
            for (int h8 = 0; h8 < 2; h8++) {
                const int row = wig * 32 + m * 16 + gid + h8 * 8;
                const int b = b0 + row;
                float x0f = 0.f, x1f = 0.f, x2f = 0.f;
                if (!WITHX) {
                    x0f = x3[(size_t)b * x3_stride + 0];
                    x1f = x3[(size_t)b * x3_stride + 1];
                    x2f = x3[(size_t)b * x3_stride + 2];
                }
#pragma unroll
                for (int nb = 0; nb < 4; nb++) {
                    const int j = j0 + nb * 8 + tig * 2;      // pair (j, j+1)
                    const size_t idx = (size_t)b * HID + j;
                    __half2 hp2 = *(const __half2*)(h_in + idx);
                    float hnew[2];
#pragma unroll
                    for (int cc = 0; cc < 2; cc++) {
                        const int jj = j + cc;
                        const int fi = h8 * 2 + cc;
                        float hr = acc[0][m][nb][fi] + b_hh[jj];
                        float hz = acc[1][m][nb][fi] + b_hh[HID + jj];
                        float hn = acc[2][m][nb][fi] + b_hh[2 * HID + jj];
                        float ir, iz, in_;
                        if (WITHX) {
                            const int col = nb * 8 + tig * 2 + cc;
                            ir  = exch[(0 * 128 + row) * EXS + col] + b_ih[jj];
                            iz  = exch[(1 * 128 + row) * EXS + col] + b_ih[HID + jj];
                            in_ = exch[(2 * 128 + row) * EXS + col] + b_ih[2 * HID + jj];
                        } else {
                            const float* w0 = &wih3[(size_t)jj * 3];
                            const float* w1 = &wih3[(size_t)(HID + jj) * 3];
                            const float* w2 = &wih3[(size_t)(2 * HID + jj) * 3];
                            ir  = x0f * w0[0] + x1f * w0[1] + x2f * w0[2] + b_ih[jj];
                            iz  = x0f * w1[0] + x1f * w1[1] + x2f * w1[2] + b_ih[HID + jj];
                            in_ = x0f * w2[0] + x1f * w2[1] + x2f * w2[2] + b_ih[2 * HID + jj];
                        }
                        float r = sigmoidf_(ir + hr);
                        float z = sigmoidf_(iz + hz);
                        float n = tanhf_(in_ + r * hn);
                        float hp = __half2float(cc == 0 ? __low2half(hp2) : __high2half(hp2));
                        hnew[cc] = (1.0f - z) * n + z * hp;
                    }
                    *(__half2*)(h_out + idx) = __floats2half2_rn(hnew[0], hnew[1]);
                }
            }
    }
}

// ---------------- output head ----------------
__global__ void fc_kernel(const h16* __restrict__ h,
                          const float* __restrict__ fc_W, const float* __restrict__ fc_b,
                          float* __restrict__ out, int out_stride)
{
    int warp = (blockIdx.x * blockDim.x + threadIdx.x) >> 5;
    int lane = threadIdx.x & 31;
    if (warp >= BATCH) return;
    float a0 = 0.f, a1 = 0.f, a2 = 0.f;
    for (int k = lane; k < HID; k += 32) {
        float hv = __half2float(h[(size_t)warp * HID + k]);
        a0 += hv * fc_W[k];
        a1 += hv * fc_W[HID + k];
        a2 += hv * fc_W[2 * HID + k];
    }
#pragma unroll
    for (int off = 16; off > 0; off >>= 1) {
        a0 += __shfl_down_sync(0xffffffffu, a0, off);
        a1 += __shfl_down_sync(0xffffffffu, a1, off);
        a2 += __shfl_down_sync(0xffffffffu, a2, off);
    }
    if (lane == 0) {
        float* o = &out[(size_t)warp * out_stride];
        o[0] = a0 + fc_b[0];
        o[1] = a1 + fc_b[1];
        o[2] = a2 + fc_b[2];
    }
}

// ---------------- launcher ----------------
extern "C" void kernel_launch(void* const* d_in, const int* in_sizes, int n_in,
                              void* d_out, int out_size)
{
    const float* x_input   = (const float*)d_in[0];
    const float* enc_W_ih0 = (const float*)d_in[2];
    const float* enc_W_hh0 = (const float*)d_in[3];
    const float* enc_b_ih0 = (const float*)d_in[4];
    const float* enc_b_hh0 = (const float*)d_in[5];
    const float* enc_W_ih1 = (const float*)d_in[6];
    const float* enc_W_hh1 = (const float*)d_in[7];
    const float* enc_b_ih1 = (const float*)d_in[8];
    const float* enc_b_hh1 = (const float*)d_in[9];
    const float* dec_W_ih0 = (const float*)d_in[10];
    const float* dec_W_hh0 = (const float*)d_in[11];
    const float* dec_b_ih0 = (const float*)d_in[12];
    const float* dec_b_hh0 = (const float*)d_in[13];
    const float* dec_W_ih1 = (const float*)d_in[14];
    const float* dec_W_hh1 = (const float*)d_in[15];
    const float* dec_b_ih1 = (const float*)d_in[16];
    const float* dec_b_hh1 = (const float*)d_in[17];
    const float* fc_W      = (const float*)d_in[18];
    const float* fc_b      = (const float*)d_in[19];
    float* out = (float*)d_out;

    const int F = out_size / (BATCH * 3);

    // stage sizes in halfs -> bytes
    const int stage1 = (2 * 128 * PS + 2 * 96 * PS) * (int)sizeof(h16);  // 21504 B
    const int stage0 = (1 * 256 * PS + 1 * 96 * PS) * (int)sizeof(h16);  // 16896 B
    cudaFuncSetAttribute(gru_mma_kernel<true>,  cudaFuncAttributeMaxDynamicSharedMemorySize, NST * stage1);
    cudaFuncSetAttribute(gru_mma_kernel<false>, cudaFuncAttributeMaxDynamicSharedMemorySize, NST * stage0);

    h16 *h0_b, *h1_b, *w_b;
    cudaGetSymbolAddress((void**)&h0_b, g_h0);
    cudaGetSymbolAddress((void**)&h1_b, g_h1);
    cudaGetSymbolAddress((void**)&w_b,  g_w);
    const size_t HN = (size_t)BATCH * HID;
    h16* h0[2] = { h0_b, h0_b + HN };
    h16* h1[2] = { h1_b, h1_b + HN };
    auto W = [&](int m) { return w_b + (size_t)m * WELEMS; };

    prep_kernel<<<2048, 256>>>(enc_W_hh0, enc_W_ih1, enc_W_hh1,
                               dec_W_hh0, dec_W_ih1, dec_W_hh1);
    zero_kernel<<<2048, 256>>>();

    dim3 grid1(HID / BJ, BATCH / 128);   // (16, 256)
    dim3 grid0(HID / BJ, BATCH / 256);   // (16, 128)
    int p0 = 0, p1 = 0;

    // ---- encoder ----
    for (int t = 0; t < T_HIST; t++) {
        gru_mma_kernel<false><<<grid0, 256, NST * stage0>>>(
            nullptr, x_input + t * 3, T_HIST * 3,
            h0[p0],
            nullptr, enc_W_ih0,
            W(0),
            enc_b_ih0, enc_b_hh0,
            h0[p0 ^ 1]);
        p0 ^= 1;
        gru_mma_kernel<true><<<grid1, 256, NST * stage1>>>(
            h0[p0], nullptr, 0,
            h1[p1],
            W(1), nullptr,
            W(2),
            enc_b_ih1, enc_b_hh1,
            h1[p1 ^ 1]);
        p1 ^= 1;
    }

    // ---- decoder ----
    for (int t = 0; t < F; t++) {
        const float* xin = (t == 0) ? (x_input + (T_HIST - 1) * 3) : (out + (t - 1) * 3);
        int xs = (t == 0) ? (T_HIST * 3) : (F * 3);
        gru_mma_kernel<false><<<grid0, 256, NST * stage0>>>(
            nullptr, xin, xs,
            h0[p0],
            nullptr, dec_W_ih0,
            W(3),
            dec_b_ih0, dec_b_hh0,
            h0[p0 ^ 1]);
        p0 ^= 1;
        gru_mma_kernel<true><<<grid1, 256, NST * stage1>>>(
            h0[p0], nullptr, 0,
            h1[p1],
            W(4), nullptr,
            W(5),
            dec_b_ih1, dec_b_hh1,
            h1[p1 ^ 1]);
        p1 ^= 1;
        fc_kernel<<<(BATCH * 32) / 256, 256>>>(h1[p1], fc_W, fc_b, out + t * 3, F * 3);
    }
}

// round 12
// speedup vs baseline: 5.5584x; 1.9915x over previous
#include <cuda_runtime.h>
#include <cuda_fp16.h>
#include <math.h>
#include <stdint.h>

#define BATCH 32768
#define HID   512
#define T_HIST 50
#define BJ 32            // hidden cols per gate per CTA
#define KC 16            // K chunk (one mma k16)
#define PS 24            // padded smem row stride (halfs) -> conflict-free ldsm
#define NST 3            // pipeline stages
#define NCH (HID / KC)   // 32

typedef __half h16;

// ---------------- device-global scratch (allocation-free) ----------------
__device__ h16 g_h0[2][(size_t)BATCH * HID];
__device__ h16 g_h1[2][(size_t)BATCH * HID];
#define WELEMS ((size_t)3 * HID * HID)
// [0]=enc_hh0 [1]=enc_ih1 [2]=enc_hh1 [3]=dec_hh0 [4]=dec_ih1 [5]=dec_hh1
__device__ h16 g_w[6][WELEMS];

// ---------------- helpers ----------------
__device__ __forceinline__ float sigmoidf_(float x) { return 1.0f / (1.0f + __expf(-x)); }
__device__ __forceinline__ float tanhf_(float x) {
    x = fminf(15.0f, fmaxf(-15.0f, x));
    float e = __expf(2.0f * x);
    return (e - 1.0f) / (e + 1.0f);
}
__device__ __forceinline__ uint32_t smem_u32(const void* p) {
    return (uint32_t)__cvta_generic_to_shared(p);
}
__device__ __forceinline__ void cp16(uint32_t dst, const void* src) {
    asm volatile("cp.async.cg.shared.global [%0], [%1], 16;" :: "r"(dst), "l"(src));
}
__device__ __forceinline__ void cp_commit() { asm volatile("cp.async.commit_group;"); }
__device__ __forceinline__ void ldsm4(uint32_t& r0, uint32_t& r1, uint32_t& r2, uint32_t& r3, uint32_t addr) {
    asm volatile("ldmatrix.sync.aligned.m8n8.x4.shared.b16 {%0,%1,%2,%3}, [%4];"
                 : "=r"(r0), "=r"(r1), "=r"(r2), "=r"(r3) : "r"(addr));
}
__device__ __forceinline__ void mma16816(float* c, const uint32_t* a, const uint32_t* b) {
    asm volatile("mma.sync.aligned.m16n8k16.row.col.f32.f16.f16.f32 "
                 "{%0,%1,%2,%3}, {%4,%5,%6,%7}, {%8,%9}, {%0,%1,%2,%3};"
                 : "+f"(c[0]), "+f"(c[1]), "+f"(c[2]), "+f"(c[3])
                 : "r"(a[0]), "r"(a[1]), "r"(a[2]), "r"(a[3]), "r"(b[0]), "r"(b[1]));
}

// ---------------- setup kernels ----------------
__global__ void prep_kernel(const float* w0, const float* w1, const float* w2,
                            const float* w3, const float* w4, const float* w5) {
    const float* srcs[6] = {w0, w1, w2, w3, w4, w5};
    size_t total = 6 * WELEMS;
    for (size_t i = (size_t)blockIdx.x * blockDim.x + threadIdx.x; i < total;
         i += (size_t)gridDim.x * blockDim.x) {
        int m = (int)(i / WELEMS);
        size_t e = i % WELEMS;
        g_w[m][e] = __float2half(srcs[m][e]);
    }
}

__global__ void zero_kernel() {
    size_t n = (size_t)BATCH * HID;
    h16 z = __float2half(0.0f);
    for (size_t i = (size_t)blockIdx.x * blockDim.x + threadIdx.x; i < n;
         i += (size_t)gridDim.x * blockDim.x) {
        g_h0[0][i] = z;
        g_h1[0][i] = z;
    }
}

// ---------------- fused GRU cell on fp16 mma.sync ----------------
// WITHX=true : 8 warps, 2 groups of 4; group0: W_hh x h, group1: W_ih x x.
//              BM = 128; smem exchange of ih gate pre-activations.
// WITHX=false: 8 warps, single group, Mw=32 -> BM = 256; W_ih0 (D=3) in fp32 epilogue.
// __launch_bounds__(256, 2): cap regs at 128 -> 2 CTAs/SM (16 warps).
template <bool WITHX>
__global__ void __launch_bounds__(256, 2)
gru_mma_kernel(const h16* __restrict__ x16,
               const float* __restrict__ x3, int x3_stride,
               const h16* __restrict__ h_in,
               const h16* __restrict__ wih, const float* __restrict__ wih3,
               const h16* __restrict__ whh,
               const float* __restrict__ b_ih, const float* __restrict__ b_hh,
               h16* __restrict__ h_out)
{
    extern __shared__ h16 smem[];
    constexpr int BM   = WITHX ? 128 : 256;
    constexpr int AROWS = WITHX ? 128 : 256;     // rows per A plane
    constexpr int NA   = WITHX ? 2 : 1;
    constexpr int NW   = WITHX ? 2 : 1;
    constexpr int APL  = AROWS * PS;             // halfs per A plane
    constexpr int AOFF = NA * APL;               // == 6144 both cases
    constexpr int WPL  = 96 * PS;
    constexpr int STAGE = AOFF + NW * WPL;       // halfs
    constexpr int EXS = 33;                      // exchange row stride (floats)

    const int tid  = threadIdx.x;
    const int lane = tid & 31;
    const int warp = tid >> 5;
    const int grp  = WITHX ? (warp >> 2) : 0;
    const int wig  = WITHX ? (warp & 3) : warp;   // warp-in-group: rows wig*32..+31
    const int j0 = blockIdx.x * BJ;
    const int b0 = blockIdx.y * BM;
    const int gid = lane >> 2, tig = lane & 3;

    const h16* gA[2] = { h_in, x16 };
    const h16* gW[2] = { whh, wih };

    float acc[3][2][4][4];   // [gate][m-frag][nb][c]
#pragma unroll
    for (int g = 0; g < 3; g++)
#pragma unroll
        for (int m = 0; m < 2; m++)
#pragma unroll
            for (int nb = 0; nb < 4; nb++)
#pragma unroll
                for (int k = 0; k < 4; k++) acc[g][m][nb][k] = 0.0f;

    auto load_stage = [&](int slot, int c) {
        h16* st = smem + slot * STAGE;
        const int k0 = c * KC;
        // A planes: NA * AROWS rows * 2 segs of 16B  (= 512 cp16 both cases)
#pragma unroll
        for (int i = tid; i < NA * AROWS * 2; i += 256) {
            int pl  = WITHX ? (i >> 8) : 0;
            int rem = WITHX ? (i & 255) : i;
            int row = rem >> 1, seg = rem & 1;
            cp16(smem_u32(st + pl * APL + row * PS + seg * 8),
                 gA[pl] + (size_t)(b0 + row) * HID + k0 + seg * 8);
        }
        // W planes: NW * 96 rows * 2 segs
#pragma unroll
        for (int i = tid; i < NW * 192; i += 256) {
            int pl = i / 192, rem = i % 192;
            int row = rem >> 1, seg = rem & 1;
            int g = row >> 5, jj = row & 31;
            cp16(smem_u32(st + AOFF + pl * WPL + row * PS + seg * 8),
                 gW[pl] + (size_t)(g * HID + j0 + jj) * HID + k0 + seg * 8);
        }
        cp_commit();
    };

    auto compute = [&](int slot) {
        h16* st = smem + slot * STAGE;
        // A fragments: 2 x m16k16 (rows wig*32 .. +31) from this group's plane
        uint32_t Af[2][4];
        const int a_row = lane & 15;
        const int a_col = (lane >> 4) * 8;
#pragma unroll
        for (int m = 0; m < 2; m++) {
            uint32_t addr = smem_u32(st + grp * APL + (wig * 32 + m * 16 + a_row) * PS + a_col);
            ldsm4(Af[m][0], Af[m][1], Af[m][2], Af[m][3], addr);
        }
        const int q = lane >> 3, mr = lane & 7;
#pragma unroll
        for (int g = 0; g < 3; g++) {
            uint32_t Bf[4][2];
            h16* base = st + AOFF + grp * WPL + (g * 32) * PS;
#pragma unroll
            for (int half = 0; half < 2; half++) {
                uint32_t addr = smem_u32(base + (half * 16 + (q >> 1) * 8 + mr) * PS + (q & 1) * 8);
                ldsm4(Bf[half * 2][0], Bf[half * 2][1],
                      Bf[half * 2 + 1][0], Bf[half * 2 + 1][1], addr);
            }
#pragma unroll
            for (int m = 0; m < 2; m++)
#pragma unroll
                for (int nb = 0; nb < 4; nb++)
                    mma16816(acc[g][m][nb], Af[m], Bf[nb]);
        }
    };

    // ---- 3-stage pipeline, one sync per chunk ----
    load_stage(0, 0);
    load_stage(1, 1);
    for (int c = 0; c < NCH; c++) {
        if (c + 1 < NCH) asm volatile("cp.async.wait_group 1;");
        else             asm volatile("cp.async.wait_group 0;");
        __syncthreads();
        if (c + 2 < NCH) load_stage((c + 2) % NST, c + 2);
        compute(c % NST);
    }

    // ---- epilogue ----
    float* exch = (float*)smem;       // overlay on dead pipeline stages
    __syncthreads();                  // everyone done reading smem

    if (WITHX && grp == 1) {
        // publish ih gate pre-activations
#pragma unroll
        for (int m = 0; m < 2; m++)
#pragma unroll
            for (int h8 = 0; h8 < 2; h8++) {
                const int row = wig * 32 + m * 16 + gid + h8 * 8;
#pragma unroll
                for (int nb = 0; nb < 4; nb++)
#pragma unroll
                    for (int cc = 0; cc < 2; cc++) {
                        const int col = nb * 8 + tig * 2 + cc;
#pragma unroll
                        for (int g = 0; g < 3; g++)
                            exch[(g * 128 + row) * EXS + col] = acc[g][m][nb][h8 * 2 + cc];
                    }
            }
    }
    if (WITHX) __syncthreads();

    if (grp == 0) {
#pragma unroll
        for (int m = 0; m < 2; m++)
#pragma unroll
            for (int h8 = 0; h8 < 2; h8++) {
                const int row = wig * 32 + m * 16 + gid + h8 * 8;
                const int b = b0 + row;
                float x0f = 0.f, x1f = 0.f, x2f = 0.f;
                if (!WITHX) {
                    x0f = x3[(size_t)b * x3_stride + 0];
                    x1f = x3[(size_t)b * x3_stride + 1];
                    x2f = x3[(size_t)b * x3_stride + 2];
                }
#pragma unroll
                for (int nb = 0; nb < 4; nb++) {
                    const int j = j0 + nb * 8 + tig * 2;      // pair (j, j+1)
                    const size_t idx = (size_t)b * HID + j;
                    __half2 hp2 = *(const __half2*)(h_in + idx);
                    float hnew[2];
#pragma unroll
                    for (int cc = 0; cc < 2; cc++) {
                        const int jj = j + cc;
                        const int fi = h8 * 2 + cc;
                        float hr = acc[0][m][nb][fi] + b_hh[jj];
                        float hz = acc[1][m][nb][fi] + b_hh[HID + jj];
                        float hn = acc[2][m][nb][fi] + b_hh[2 * HID + jj];
                        float ir, iz, in_;
                        if (WITHX) {
                            const int col = nb * 8 + tig * 2 + cc;
                            ir  = exch[(0 * 128 + row) * EXS + col] + b_ih[jj];
                            iz  = exch[(1 * 128 + row) * EXS + col] + b_ih[HID + jj];
                            in_ = exch[(2 * 128 + row) * EXS + col] + b_ih[2 * HID + jj];
                        } else {
                            const float* w0 = &wih3[(size_t)jj * 3];
                            const float* w1 = &wih3[(size_t)(HID + jj) * 3];
                            const float* w2 = &wih3[(size_t)(2 * HID + jj) * 3];
                            ir  = x0f * w0[0] + x1f * w0[1] + x2f * w0[2] + b_ih[jj];
                            iz  = x0f * w1[0] + x1f * w1[1] + x2f * w1[2] + b_ih[HID + jj];
                            in_ = x0f * w2[0] + x1f * w2[1] + x2f * w2[2] + b_ih[2 * HID + jj];
                        }
                        float r = sigmoidf_(ir + hr);
                        float z = sigmoidf_(iz + hz);
                        float n = tanhf_(in_ + r * hn);
                        float hp = __half2float(cc == 0 ? __low2half(hp2) : __high2half(hp2));
                        hnew[cc] = (1.0f - z) * n + z * hp;
                    }
                    *(__half2*)(h_out + idx) = __floats2half2_rn(hnew[0], hnew[1]);
                }
            }
    }
}

// ---------------- output head ----------------
__global__ void fc_kernel(const h16* __restrict__ h,
                          const float* __restrict__ fc_W, const float* __restrict__ fc_b,
                          float* __restrict__ out, int out_stride)
{
    int warp = (blockIdx.x * blockDim.x + threadIdx.x) >> 5;
    int lane = threadIdx.x & 31;
    if (warp >= BATCH) return;
    float a0 = 0.f, a1 = 0.f, a2 = 0.f;
    for (int k = lane; k < HID; k += 32) {
        float hv = __half2float(h[(size_t)warp * HID + k]);
        a0 += hv * fc_W[k];
        a1 += hv * fc_W[HID + k];
        a2 += hv * fc_W[2 * HID + k];
    }
#pragma unroll
    for (int off = 16; off > 0; off >>= 1) {
        a0 += __shfl_down_sync(0xffffffffu, a0, off);
        a1 += __shfl_down_sync(0xffffffffu, a1, off);
        a2 += __shfl_down_sync(0xffffffffu, a2, off);
    }
    if (lane == 0) {
        float* o = &out[(size_t)warp * out_stride];
        o[0] = a0 + fc_b[0];
        o[1] = a1 + fc_b[1];
        o[2] = a2 + fc_b[2];
    }
}

// ---------------- launcher ----------------
extern "C" void kernel_launch(void* const* d_in, const int* in_sizes, int n_in,
                              void* d_out, int out_size)
{
    const float* x_input   = (const float*)d_in[0];
    const float* enc_W_ih0 = (const float*)d_in[2];
    const float* enc_W_hh0 = (const float*)d_in[3];
    const float* enc_b_ih0 = (const float*)d_in[4];
    const float* enc_b_hh0 = (const float*)d_in[5];
    const float* enc_W_ih1 = (const float*)d_in[6];
    const float* enc_W_hh1 = (const float*)d_in[7];
    const float* enc_b_ih1 = (const float*)d_in[8];
    const float* enc_b_hh1 = (const float*)d_in[9];
    const float* dec_W_ih0 = (const float*)d_in[10];
    const float* dec_W_hh0 = (const float*)d_in[11];
    const float* dec_b_ih0 = (const float*)d_in[12];
    const float* dec_b_hh0 = (const float*)d_in[13];
    const float* dec_W_ih1 = (const float*)d_in[14];
    const float* dec_W_hh1 = (const float*)d_in[15];
    const float* dec_b_ih1 = (const float*)d_in[16];
    const float* dec_b_hh1 = (const float*)d_in[17];
    const float* fc_W      = (const float*)d_in[18];
    const float* fc_b      = (const float*)d_in[19];
    float* out = (float*)d_out;

    const int F = out_size / (BATCH * 3);

    // stage sizes in halfs -> bytes
    const int stage1 = (2 * 128 * PS + 2 * 96 * PS) * (int)sizeof(h16);  // 21504 B
    const int stage0 = (1 * 256 * PS + 1 * 96 * PS) * (int)sizeof(h16);  // 16896 B
    cudaFuncSetAttribute(gru_mma_kernel<true>,  cudaFuncAttributeMaxDynamicSharedMemorySize, NST * stage1);
    cudaFuncSetAttribute(gru_mma_kernel<false>, cudaFuncAttributeMaxDynamicSharedMemorySize, NST * stage0);

    h16 *h0_b, *h1_b, *w_b;
    cudaGetSymbolAddress((void**)&h0_b, g_h0);
    cudaGetSymbolAddress((void**)&h1_b, g_h1);
    cudaGetSymbolAddress((void**)&w_b,  g_w);
    const size_t HN = (size_t)BATCH * HID;
    h16* h0[2] = { h0_b, h0_b + HN };
    h16* h1[2] = { h1_b, h1_b + HN };
    auto W = [&](int m) { return w_b + (size_t)m * WELEMS; };

    prep_kernel<<<2048, 256>>>(enc_W_hh0, enc_W_ih1, enc_W_hh1,
                               dec_W_hh0, dec_W_ih1, dec_W_hh1);
    zero_kernel<<<2048, 256>>>();

    dim3 grid1(HID / BJ, BATCH / 128);   // (16, 256)
    dim3 grid0(HID / BJ, BATCH / 256);   // (16, 128)
    int p0 = 0, p1 = 0;

    // ---- encoder ----
    for (int t = 0; t < T_HIST; t++) {
        gru_mma_kernel<false><<<grid0, 256, NST * stage0>>>(
            nullptr, x_input + t * 3, T_HIST * 3,
            h0[p0],
            nullptr, enc_W_ih0,
            W(0),
            enc_b_ih0, enc_b_hh0,
            h0[p0 ^ 1]);
        p0 ^= 1;
        gru_mma_kernel<true><<<grid1, 256, NST * stage1>>>(
            h0[p0], nullptr, 0,
            h1[p1],
            W(1), nullptr,
            W(2),
            enc_b_ih1, enc_b_hh1,
            h1[p1 ^ 1]);
        p1 ^= 1;
    }

    // ---- decoder ----
    for (int t = 0; t < F; t++) {
        const float* xin = (t == 0) ? (x_input + (T_HIST - 1) * 3) : (out + (t - 1) * 3);
        int xs = (t == 0) ? (T_HIST * 3) : (F * 3);
        gru_mma_kernel<false><<<grid0, 256, NST * stage0>>>(
            nullptr, xin, xs,
            h0[p0],
            nullptr, dec_W_ih0,
            W(3),
            dec_b_ih0, dec_b_hh0,
            h0[p0 ^ 1]);
        p0 ^= 1;
        gru_mma_kernel<true><<<grid1, 256, NST * stage1>>>(
            h0[p0], nullptr, 0,
            h1[p1],
            W(4), nullptr,
            W(5),
            dec_b_ih1, dec_b_hh1,
            h1[p1 ^ 1]);
        p1 ^= 1;
        fc_kernel<<<(BATCH * 32) / 256, 256>>>(h1[p1], fc_W, fc_b, out + t * 3, F * 3);
    }
}